// round 2
// baseline (speedup 1.0000x reference)
#include <cuda_runtime.h>
#include <math.h>

// ---------------- problem constants ----------------
constexpr int T    = 2048;
constexpr int H    = 1024;
constexpr int NH   = 16;
constexpr int NKV  = 4;
constexpr int HD   = 64;
constexpr int NE   = 8;
constexpr int F    = 2048;
constexpr int QKVD = (NH + 2 * NKV) * HD;   // 1536
constexpr float EPS = 1e-5f;
constexpr float SM_SCALE = 0.125f;          // HD^-0.5

// ---------------- scratch (device globals; no runtime alloc) ----------------
__device__ float g_xn   [T * H];
__device__ float g_qkv  [T * QKVD];
__device__ float g_q    [NH  * T * HD];
__device__ float g_k    [NKV * T * HD];
__device__ float g_v    [NKV * T * HD];
__device__ float g_attno[T * H];
__device__ float g_x1   [T * H];
__device__ float g_xn2  [T * H];
__device__ float g_h1   [(size_t)NE * T * F];
__device__ float g_h3   [(size_t)NE * T * F];
__device__ float g_xout [T * H];
__device__ int   g_cnt  [NE];
__device__ int   g_tok  [NE * T];
__device__ float g_wt   [NE * T];

// ---------------- misc kernels ----------------
__global__ void zero_cnt_kernel() {
    if (threadIdx.x < NE) g_cnt[threadIdx.x] = 0;
}

// rmsnorm over rows of length H=1024. 256 threads -> 1 float4/thread.
__global__ __launch_bounds__(256) void rmsnorm_kernel(
    const float* __restrict__ x, const float* __restrict__ w,
    float* __restrict__ out, float* __restrict__ copy_out)
{
    int row = blockIdx.x;
    int tid = threadIdx.x;
    const float4* xr = (const float4*)(x + (size_t)row * H);
    float4 v = xr[tid];
    float ss = v.x * v.x + v.y * v.y + v.z * v.z + v.w * v.w;
#pragma unroll
    for (int o = 16; o > 0; o >>= 1) ss += __shfl_xor_sync(0xffffffffu, ss, o);
    __shared__ float warpsum[8];
    if ((tid & 31) == 0) warpsum[tid >> 5] = ss;
    __syncthreads();
    if (tid == 0) {
        float s = 0.f;
#pragma unroll
        for (int i = 0; i < 8; i++) s += warpsum[i];
        warpsum[0] = rsqrtf(s / (float)H + EPS);
    }
    __syncthreads();
    float rstd = warpsum[0];
    float4 wv = ((const float4*)w)[tid];
    float4 r;
    r.x = v.x * rstd * wv.x;
    r.y = v.y * rstd * wv.y;
    r.z = v.z * rstd * wv.z;
    r.w = v.w * rstd * wv.w;
    ((float4*)(out + (size_t)row * H))[tid] = r;
    if (copy_out) ((float4*)(copy_out + (size_t)row * H))[tid] = v;
}

// rope + qkv split. grid (T, NH + 2*NKV), 32 threads.
__global__ void rope_kernel(const float* __restrict__ qkv, const int* __restrict__ pos)
{
    int t = blockIdx.x;
    int h = blockIdx.y;
    int lane = threadIdx.x;
    if (h < NH + NKV) {
        float p = (float)pos[t];
        // inv_freq = 10000^(-lane/32)
        float inv = exp2f(-(float)lane * (13.287712379549449f / 32.0f));
        float ang = p * inv;
        float s, c;
        sincosf(ang, &s, &c);
        const float* src;
        float* dst;
        if (h < NH) {
            src = qkv + (size_t)t * QKVD + h * HD;
            dst = g_q + ((size_t)h * T + t) * HD;
        } else {
            int kh = h - NH;
            src = qkv + (size_t)t * QKVD + NH * HD + kh * HD;
            dst = g_k + ((size_t)kh * T + t) * HD;
        }
        float x1 = src[lane], x2 = src[lane + 32];
        dst[lane]      = x1 * c - x2 * s;
        dst[lane + 32] = x2 * c + x1 * s;
    } else {
        int kh = h - NH - NKV;
        const float* src = qkv + (size_t)t * QKVD + (NH + NKV) * HD + kh * HD;
        float* dst = g_v + ((size_t)kh * T + t) * HD;
        dst[lane]      = src[lane];
        dst[lane + 32] = src[lane + 32];
    }
}

// ---------------- generic NT GEMM ----------------
// C[M,N] = A[M,K] @ B[N,K]^T  (row-major), 128x128x16 tiles, 8x8 microtile.
// mode 0: plain (+optional addsrc)
// mode 1: MoE up-proj: gather A rows via g_tok[e], M=g_cnt[e], B/C offset by expert
// mode 2: MoE down-proj: A rows = expert slot, scatter atomicAdd into Cbase with weight
constexpr int BM = 128, BN = 128, BK = 16;

__global__ __launch_bounds__(256, 2) void gemm_kernel(
    int mode, int Mfull, int N, int K,
    const float* __restrict__ Abase, const float* __restrict__ Bbase,
    float* __restrict__ Cbase, const float* __restrict__ addsrc)
{
    __shared__ float As[BK][BM + 4];
    __shared__ float Bs[BK][BN + 4];
    __shared__ const float* rowA[BM];

    int e = blockIdx.z;
    int M = Mfull;
    const float* A = Abase;
    const float* B = Bbase;
    const int* tok = nullptr;
    const float* wts = nullptr;
    if (mode == 1) {
        M = g_cnt[e];
        B = Bbase + (size_t)e * N * K;
        tok = g_tok + e * T;
    } else if (mode == 2) {
        M = g_cnt[e];
        A = Abase + (size_t)e * T * K;
        B = Bbase + (size_t)e * N * K;
        tok = g_tok + e * T;
        wts = g_wt + e * T;
    }
    int m0 = blockIdx.y * BM;
    int n0 = blockIdx.x * BN;
    if (m0 >= M) return;

    int tid = threadIdx.x;
    if (tid < BM) {
        int m = m0 + tid;
        int r = (m < M) ? m : (M - 1);
        if (mode == 1) r = tok[r];
        rowA[tid] = A + (size_t)r * K;
    }
    __syncthreads();

    int tx = tid & 15, ty = tid >> 4;
    float acc[8][8];
#pragma unroll
    for (int i = 0; i < 8; i++)
#pragma unroll
        for (int j = 0; j < 8; j++) acc[i][j] = 0.f;

    int ar0 = tid >> 2;          // 0..63
    int ar1 = ar0 + 64;          // 64..127
    int ac0 = (tid & 3) * 4;     // 0,4,8,12
    const float* brow0 = B + (size_t)(n0 + ar0) * K + ac0;
    const float* brow1 = B + (size_t)(n0 + ar1) * K + ac0;

    int ktiles = K / BK;
    float4 pa0, pa1, pb0, pb1;
    pa0 = *(const float4*)(rowA[ar0] + ac0);
    pa1 = *(const float4*)(rowA[ar1] + ac0);
    pb0 = *(const float4*)(brow0);
    pb1 = *(const float4*)(brow1);

#define STORE_TILES() do { \
    As[ac0+0][ar0]=pa0.x; As[ac0+1][ar0]=pa0.y; As[ac0+2][ar0]=pa0.z; As[ac0+3][ar0]=pa0.w; \
    As[ac0+0][ar1]=pa1.x; As[ac0+1][ar1]=pa1.y; As[ac0+2][ar1]=pa1.z; As[ac0+3][ar1]=pa1.w; \
    Bs[ac0+0][ar0]=pb0.x; Bs[ac0+1][ar0]=pb0.y; Bs[ac0+2][ar0]=pb0.z; Bs[ac0+3][ar0]=pb0.w; \
    Bs[ac0+0][ar1]=pb1.x; Bs[ac0+1][ar1]=pb1.y; Bs[ac0+2][ar1]=pb1.z; Bs[ac0+3][ar1]=pb1.w; \
} while (0)

    STORE_TILES();
    __syncthreads();

    for (int kt = 0; kt < ktiles; kt++) {
        bool has = (kt + 1 < ktiles);
        if (has) {
            int kn = (kt + 1) * BK;
            pa0 = *(const float4*)(rowA[ar0] + kn + ac0);
            pa1 = *(const float4*)(rowA[ar1] + kn + ac0);
            pb0 = *(const float4*)(brow0 + kn);
            pb1 = *(const float4*)(brow1 + kn);
        }
#pragma unroll
        for (int kk = 0; kk < BK; kk++) {
            float a[8], b[8];
            *(float4*)(a)     = *(const float4*)&As[kk][ty * 8];
            *(float4*)(a + 4) = *(const float4*)&As[kk][ty * 8 + 4];
            *(float4*)(b)     = *(const float4*)&Bs[kk][tx * 8];
            *(float4*)(b + 4) = *(const float4*)&Bs[kk][tx * 8 + 4];
#pragma unroll
            for (int i = 0; i < 8; i++)
#pragma unroll
                for (int j = 0; j < 8; j++)
                    acc[i][j] = fmaf(a[i], b[j], acc[i][j]);
        }
        if (has) {
            __syncthreads();
            STORE_TILES();
            __syncthreads();
        }
    }
#undef STORE_TILES

    if (mode == 2) {
#pragma unroll
        for (int i = 0; i < 8; i++) {
            int m = m0 + ty * 8 + i;
            if (m < M) {
                int t2 = tok[m];
                float wgt = wts[m];
                float* orow = Cbase + (size_t)t2 * N + n0 + tx * 8;
#pragma unroll
                for (int j = 0; j < 8; j++)
                    atomicAdd(orow + j, wgt * acc[i][j]);
            }
        }
    } else {
        float* C = (mode == 1) ? (Cbase + (size_t)e * T * N) : Cbase;
#pragma unroll
        for (int i = 0; i < 8; i++) {
            int m = m0 + ty * 8 + i;
            if (m < M) {
                float* crow = C + (size_t)m * N + n0 + tx * 8;
                float4 r0 = make_float4(acc[i][0], acc[i][1], acc[i][2], acc[i][3]);
                float4 r1 = make_float4(acc[i][4], acc[i][5], acc[i][6], acc[i][7]);
                if (addsrc) {
                    const float4* ar = (const float4*)(addsrc + (size_t)m * N + n0 + tx * 8);
                    float4 a0 = ar[0], a1 = ar[1];
                    r0.x += a0.x; r0.y += a0.y; r0.z += a0.z; r0.w += a0.w;
                    r1.x += a1.x; r1.y += a1.y; r1.z += a1.z; r1.w += a1.w;
                }
                ((float4*)crow)[0] = r0;
                ((float4*)crow)[1] = r1;
            }
        }
    }
}

// ---------------- flash attention (fp32, causal, GQA) ----------------
constexpr int BQ = 64;
constexpr int ATTN_SMEM_BYTES = (3 * 64 * (BQ + 4) + 64 * BQ) * 4;  // 68608

__global__ __launch_bounds__(256, 2) void attn_kernel()
{
    extern __shared__ float sm[];
    float (*Qt)[BQ + 4] = (float (*)[BQ + 4])sm;
    float (*Kt)[BQ + 4] = (float (*)[BQ + 4])(sm + 64 * (BQ + 4));
    float (*Ps)[BQ + 4] = (float (*)[BQ + 4])(sm + 2 * 64 * (BQ + 4));
    float (*Vs)[BQ]     = (float (*)[BQ])(sm + 3 * 64 * (BQ + 4));

    int qb = blockIdx.x;
    int h  = blockIdx.y;
    int kh = h >> 2;  // NH/NKV = 4
    int tid = threadIdx.x, tx = tid & 15, ty = tid >> 4;

    // load Q transposed (scaled)
    const float* Qg = g_q + ((size_t)h * T + qb * BQ) * HD;
    {
        int i = tid >> 2;
#pragma unroll
        for (int it = 0; it < 4; it++) {
            int d0 = ((tid & 3) + it * 4) * 4;
            float4 v = *(const float4*)(Qg + (size_t)i * HD + d0);
            Qt[d0 + 0][i] = v.x * SM_SCALE;
            Qt[d0 + 1][i] = v.y * SM_SCALE;
            Qt[d0 + 2][i] = v.z * SM_SCALE;
            Qt[d0 + 3][i] = v.w * SM_SCALE;
        }
    }

    float m_i[4], l_i[4], o[4][4];
#pragma unroll
    for (int a = 0; a < 4; a++) {
        m_i[a] = -1e30f;
        l_i[a] = 0.f;
#pragma unroll
        for (int b = 0; b < 4; b++) o[a][b] = 0.f;
    }

    for (int kb = 0; kb <= qb; kb++) {
        __syncthreads();
        const float* Kg = g_k + ((size_t)kh * T + kb * BQ) * HD;
        const float* Vg = g_v + ((size_t)kh * T + kb * BQ) * HD;
        {
            int i = tid >> 2;
#pragma unroll
            for (int it = 0; it < 4; it++) {
                int d0 = ((tid & 3) + it * 4) * 4;
                float4 v = *(const float4*)(Kg + (size_t)i * HD + d0);
                Kt[d0 + 0][i] = v.x;
                Kt[d0 + 1][i] = v.y;
                Kt[d0 + 2][i] = v.z;
                Kt[d0 + 3][i] = v.w;
            }
#pragma unroll
            for (int it = 0; it < 4; it++) {
                int f = tid + it * 256;
                int r = f >> 4, c0 = (f & 15) * 4;
                *(float4*)&Vs[r][c0] = *(const float4*)(Vg + (size_t)r * HD + c0);
            }
        }
        __syncthreads();

        // S = Q K^T (scaled already)
        float s[4][4];
#pragma unroll
        for (int a = 0; a < 4; a++)
#pragma unroll
            for (int b = 0; b < 4; b++) s[a][b] = 0.f;
#pragma unroll
        for (int d = 0; d < HD; d++) {
            float4 av = *(const float4*)&Qt[d][ty * 4];
            float4 bv = *(const float4*)&Kt[d][tx * 4];
            float aa[4] = {av.x, av.y, av.z, av.w};
            float bb[4] = {bv.x, bv.y, bv.z, bv.w};
#pragma unroll
            for (int a = 0; a < 4; a++)
#pragma unroll
                for (int b = 0; b < 4; b++)
                    s[a][b] = fmaf(aa[a], bb[b], s[a][b]);
        }
        if (kb == qb) {
#pragma unroll
            for (int a = 0; a < 4; a++)
#pragma unroll
                for (int b = 0; b < 4; b++)
                    if (tx * 4 + b > ty * 4 + a) s[a][b] = -1e30f;
        }

        // online softmax over full row (reduce across tx = 16 lanes)
#pragma unroll
        for (int a = 0; a < 4; a++) {
            float rm = fmaxf(fmaxf(s[a][0], s[a][1]), fmaxf(s[a][2], s[a][3]));
#pragma unroll
            for (int off = 1; off < 16; off <<= 1)
                rm = fmaxf(rm, __shfl_xor_sync(0xffffffffu, rm, off, 16));
            float mn = fmaxf(m_i[a], rm);
            float sc = __expf(m_i[a] - mn);
            m_i[a] = mn;
            float rs = 0.f;
#pragma unroll
            for (int b = 0; b < 4; b++) {
                float p = __expf(s[a][b] - mn);
                s[a][b] = p;
                rs += p;
            }
#pragma unroll
            for (int off = 1; off < 16; off <<= 1)
                rs += __shfl_xor_sync(0xffffffffu, rs, off, 16);
            l_i[a] = l_i[a] * sc + rs;
#pragma unroll
            for (int b = 0; b < 4; b++) o[a][b] *= sc;
        }

        // P -> smem transposed: Ps[k][i]
#pragma unroll
        for (int b = 0; b < 4; b++) {
            float4 pv = make_float4(s[0][b], s[1][b], s[2][b], s[3][b]);
            *(float4*)&Ps[tx * 4 + b][ty * 4] = pv;
        }
        __syncthreads();

        // O += P V
#pragma unroll
        for (int kk = 0; kk < BQ; kk++) {
            float4 av = *(const float4*)&Ps[kk][ty * 4];
            float4 bv = *(const float4*)&Vs[kk][tx * 4];
            float aa[4] = {av.x, av.y, av.z, av.w};
            float bb[4] = {bv.x, bv.y, bv.z, bv.w};
#pragma unroll
            for (int a = 0; a < 4; a++)
#pragma unroll
                for (int b = 0; b < 4; b++)
                    o[a][b] = fmaf(aa[a], bb[b], o[a][b]);
        }
    }

#pragma unroll
    for (int a = 0; a < 4; a++) {
        float inv = 1.0f / l_i[a];
        int trow = qb * BQ + ty * 4 + a;
        float* dst = g_attno + (size_t)trow * H + h * HD + tx * 4;
        float4 r = make_float4(o[a][0] * inv, o[a][1] * inv, o[a][2] * inv, o[a][3] * inv);
        *(float4*)dst = r;
    }
}

// ---------------- MoE routing ----------------
__global__ __launch_bounds__(256) void route_kernel(const float* __restrict__ gate_w)
{
    int t = blockIdx.x;
    int wid = threadIdx.x >> 5, lane = threadIdx.x & 31;
    const float* x = g_xn2 + (size_t)t * H;
    const float* g = gate_w + (size_t)wid * H;
    float s = 0.f;
    for (int i = lane; i < H; i += 32) s += x[i] * g[i];
#pragma unroll
    for (int off = 16; off > 0; off >>= 1) s += __shfl_xor_sync(0xffffffffu, s, off);
    __shared__ float logits[NE];
    if (lane == 0) logits[wid] = s;
    __syncthreads();
    if (threadIdx.x == 0) {
        int i1 = 0;
        for (int i = 1; i < NE; i++)
            if (logits[i] > logits[i1]) i1 = i;
        int i2 = (i1 == 0) ? 1 : 0;
        for (int i = 0; i < NE; i++)
            if (i != i1 && logits[i] > logits[i2]) i2 = i;
        float e1 = 1.0f;  // exp(l1 - l1)
        float e2 = expf(logits[i2] - logits[i1]);
        float inv = 1.0f / (e1 + e2);
        float w1v = e1 * inv, w2v = e2 * inv;
        int p1 = atomicAdd(&g_cnt[i1], 1);
        g_tok[i1 * T + p1] = t;
        g_wt [i1 * T + p1] = w1v;
        int p2 = atomicAdd(&g_cnt[i2], 1);
        g_tok[i2 * T + p2] = t;
        g_wt [i2 * T + p2] = w2v;
    }
}

// silu(h1) * h3 in place into g_h1. grid (T, NE), early exit by count.
__global__ __launch_bounds__(256) void silu_kernel()
{
    int e = blockIdx.y, m = blockIdx.x;
    if (m >= g_cnt[e]) return;
    float4* h1 = (float4*)(g_h1 + ((size_t)e * T + m) * F);
    const float4* h3 = (const float4*)(g_h3 + ((size_t)e * T + m) * F);
#pragma unroll
    for (int it = 0; it < 2; it++) {
        int i = threadIdx.x + it * 256;
        float4 a = h1[i], c = h3[i];
        a.x = a.x / (1.f + __expf(-a.x)) * c.x;
        a.y = a.y / (1.f + __expf(-a.y)) * c.y;
        a.z = a.z / (1.f + __expf(-a.z)) * c.z;
        a.w = a.w / (1.f + __expf(-a.w)) * c.w;
        h1[i] = a;
    }
}

// ---------------- launcher ----------------
extern "C" void kernel_launch(void* const* d_in, const int* in_sizes, int n_in,
                              void* d_out, int out_size)
{
    const int*   positions = (const int*)  d_in[0];
    const float* hidden    = (const float*)d_in[1];
    const float* w_qkv     = (const float*)d_in[2];
    const float* w_o       = (const float*)d_in[3];
    const float* norm_in   = (const float*)d_in[4];
    const float* norm_post = (const float*)d_in[5];
    const float* norm_next = (const float*)d_in[6];
    const float* gate_w    = (const float*)d_in[7];
    const float* w1        = (const float*)d_in[8];
    const float* w2        = (const float*)d_in[9];
    const float* w3        = (const float*)d_in[10];
    float* out = (float*)d_out;

    float *p_xn, *p_qkv, *p_attno, *p_x1, *p_xn2, *p_h1, *p_h3, *p_xout;
    cudaGetSymbolAddress((void**)&p_xn,    g_xn);
    cudaGetSymbolAddress((void**)&p_qkv,   g_qkv);
    cudaGetSymbolAddress((void**)&p_attno, g_attno);
    cudaGetSymbolAddress((void**)&p_x1,    g_x1);
    cudaGetSymbolAddress((void**)&p_xn2,   g_xn2);
    cudaGetSymbolAddress((void**)&p_h1,    g_h1);
    cudaGetSymbolAddress((void**)&p_h3,    g_h3);
    cudaGetSymbolAddress((void**)&p_xout,  g_xout);

    cudaFuncSetAttribute(attn_kernel, cudaFuncAttributeMaxDynamicSharedMemorySize,
                         ATTN_SMEM_BYTES);

    // 1) reset routing counts (per replay)
    zero_cnt_kernel<<<1, 32>>>();
    // 2) xn = rmsnorm(hidden, norm_in)
    rmsnorm_kernel<<<T, 256>>>(hidden, norm_in, p_xn, nullptr);
    // 3) qkv = xn @ w_qkv^T
    gemm_kernel<<<dim3(QKVD / BN, T / BM, 1), 256>>>(0, T, QKVD, H, p_xn, w_qkv, p_qkv, nullptr);
    // 4) rope + split
    rope_kernel<<<dim3(T, NH + 2 * NKV), 32>>>(p_qkv, positions);
    // 5) attention
    attn_kernel<<<dim3(T / BQ, NH), 256, ATTN_SMEM_BYTES>>>();
    // 6) x1 = hidden + attno @ w_o^T
    gemm_kernel<<<dim3(H / BN, T / BM, 1), 256>>>(0, T, H, H, p_attno, w_o, p_x1, hidden);
    // 7) xn2 = rmsnorm(x1, norm_post); xout = x1 (residual accumulator init)
    rmsnorm_kernel<<<T, 256>>>(p_x1, norm_post, p_xn2, p_xout);
    // 8) routing (top-2)
    route_kernel<<<T, 256>>>(gate_w);
    // 9/10) h1 = gathered xn2 @ w1^T ; h3 = gathered xn2 @ w3^T
    gemm_kernel<<<dim3(F / BN, T / BM, NE), 256>>>(1, 0, F, H, p_xn2, w1, p_h1, nullptr);
    gemm_kernel<<<dim3(F / BN, T / BM, NE), 256>>>(1, 0, F, H, p_xn2, w3, p_h3, nullptr);
    // 11) act = silu(h1) * h3
    silu_kernel<<<dim3(T, NE), 256>>>();
    // 12) xout += wt * (act @ w2^T)  (atomic scatter)
    gemm_kernel<<<dim3(H / BN, T / BM, NE), 256>>>(2, 0, H, F, p_h1, w2, p_xout, nullptr);
    // 13) out = rmsnorm(xout, norm_next); out[T*H:] = xout
    float* xcopy = (out_size >= 2 * T * H) ? (out + (size_t)T * H) : nullptr;
    rmsnorm_kernel<<<T, 256>>>(p_xout, norm_next, out, xcopy);
}

// round 4
// speedup vs baseline: 1.5923x; 1.5923x over previous
#include <cuda_runtime.h>
#include <math.h>
#include <stdint.h>

// ---------------- problem constants ----------------
constexpr int T    = 2048;
constexpr int H    = 1024;
constexpr int NH   = 16;
constexpr int NKV  = 4;
constexpr int HD   = 64;
constexpr int NE   = 8;
constexpr int F    = 2048;
constexpr int QKVD = (NH + 2 * NKV) * HD;   // 1536
constexpr float EPS = 1e-5f;
constexpr float SM_SCALE = 0.125f;          // HD^-0.5

// ---------------- scratch (device globals; no runtime alloc) ----------------
__device__ float g_xn   [T * H];
__device__ float g_qkv  [T * QKVD];
__device__ float g_q    [NH  * T * HD];
__device__ float g_k    [NKV * T * HD];
__device__ float g_v    [NKV * T * HD];
__device__ float g_attno[T * H];
__device__ float g_x1   [T * H];
__device__ float g_xn2  [T * H];
__device__ float g_h1   [(size_t)NE * T * F];
__device__ float g_h3   [(size_t)NE * T * F];
__device__ float g_xout [T * H];
__device__ int   g_cnt  [NE];
__device__ int   g_tok  [NE * T];
__device__ float g_wt   [NE * T];

// ---------------- misc kernels ----------------
__global__ void zero_cnt_kernel() {
    if (threadIdx.x < NE) g_cnt[threadIdx.x] = 0;
}

// rmsnorm over rows of length H=1024. 256 threads -> 1 float4/thread.
__global__ __launch_bounds__(256) void rmsnorm_kernel(
    const float* __restrict__ x, const float* __restrict__ w,
    float* __restrict__ out, float* __restrict__ copy_out)
{
    int row = blockIdx.x;
    int tid = threadIdx.x;
    const float4* xr = (const float4*)(x + (size_t)row * H);
    float4 v = xr[tid];
    float ss = v.x * v.x + v.y * v.y + v.z * v.z + v.w * v.w;
#pragma unroll
    for (int o = 16; o > 0; o >>= 1) ss += __shfl_xor_sync(0xffffffffu, ss, o);
    __shared__ float warpsum[8];
    if ((tid & 31) == 0) warpsum[tid >> 5] = ss;
    __syncthreads();
    if (tid == 0) {
        float s = 0.f;
#pragma unroll
        for (int i = 0; i < 8; i++) s += warpsum[i];
        warpsum[0] = rsqrtf(s / (float)H + EPS);
    }
    __syncthreads();
    float rstd = warpsum[0];
    float4 wv = ((const float4*)w)[tid];
    float4 r;
    r.x = v.x * rstd * wv.x;
    r.y = v.y * rstd * wv.y;
    r.z = v.z * rstd * wv.z;
    r.w = v.w * rstd * wv.w;
    ((float4*)(out + (size_t)row * H))[tid] = r;
    if (copy_out) ((float4*)(copy_out + (size_t)row * H))[tid] = v;
}

// rope + qkv split. 8 (t,h) pairs per 256-thread block.
__global__ __launch_bounds__(256) void rope_kernel(const float* __restrict__ qkv,
                                                   const int* __restrict__ pos)
{
    int idx = blockIdx.x * 8 + (threadIdx.x >> 5);
    int t = idx / (NH + 2 * NKV);
    int h = idx % (NH + 2 * NKV);
    int lane = threadIdx.x & 31;
    if (h < NH + NKV) {
        float p = (float)pos[t];
        float inv = exp2f(-(float)lane * (13.287712379549449f / 32.0f));
        float ang = p * inv;
        float s, c;
        sincosf(ang, &s, &c);
        const float* src;
        float* dst;
        if (h < NH) {
            src = qkv + (size_t)t * QKVD + h * HD;
            dst = g_q + ((size_t)h * T + t) * HD;
        } else {
            int kh = h - NH;
            src = qkv + (size_t)t * QKVD + NH * HD + kh * HD;
            dst = g_k + ((size_t)kh * T + t) * HD;
        }
        float x1 = src[lane], x2 = src[lane + 32];
        dst[lane]      = x1 * c - x2 * s;
        dst[lane + 32] = x2 * c + x1 * s;
    } else {
        int kh = h - NH - NKV;
        const float* src = qkv + (size_t)t * QKVD + (NH + NKV) * HD + kh * HD;
        float* dst = g_v + ((size_t)kh * T + t) * HD;
        dst[lane]      = src[lane];
        dst[lane + 32] = src[lane + 32];
    }
}

// ---------------- tf32 tensor-core NT GEMM ----------------
// C[M,N] = A[M,K] @ B[N,K]^T  row-major. 128x128x32 tiles.
// 8 warps as 4(m) x 2(n); warp tile 32x64 = 2 x 8 m16n8k8 frags.
// Smem: [row][kmap(k)] with (k, k+4) interleaved adjacent -> LDS.64 frag loads.
// mode 0: plain (+optional addsrc)
// mode 1: MoE up: gather A rows via g_tok[e], M=g_cnt[e], B/C per-expert
// mode 2: MoE down: A rows = expert slot, atomic scatter into Cbase with weight
constexpr int BM = 128, BN = 128, BK = 32;
constexpr int KPAD = BK + 8;   // 40 words -> conflict-free LDS.64 frag loads

__device__ __forceinline__ uint32_t f2tf(float x) {
    uint32_t u;
    asm("cvt.rna.tf32.f32 %0, %1;" : "=r"(u) : "f"(x));
    return u;
}

__device__ __forceinline__ void mma_tf32(float* c, const uint32_t* a, const uint32_t* b) {
    asm volatile(
        "mma.sync.aligned.m16n8k8.row.col.f32.tf32.tf32.f32 "
        "{%0,%1,%2,%3}, {%4,%5,%6,%7}, {%8,%9}, {%0,%1,%2,%3};"
        : "+f"(c[0]), "+f"(c[1]), "+f"(c[2]), "+f"(c[3])
        : "r"(a[0]), "r"(a[1]), "r"(a[2]), "r"(a[3]), "r"(b[0]), "r"(b[1]));
}

__global__ __launch_bounds__(256, 2) void gemm_tf32_kernel(
    int mode, int Mfull, int N, int K,
    const float* __restrict__ Abase, const float* __restrict__ Bbase,
    float* __restrict__ Cbase, const float* __restrict__ addsrc)
{
    __shared__ uint32_t As[BM * KPAD];
    __shared__ uint32_t Bs[BN * KPAD];
    __shared__ const float* rowA[BM];

    int e = blockIdx.z;
    int M = Mfull;
    const float* A = Abase;
    const float* B = Bbase;
    const int* tok = nullptr;
    const float* wts = nullptr;
    if (mode == 1) {
        M = g_cnt[e];
        B = Bbase + (size_t)e * N * K;
        tok = g_tok + e * T;
    } else if (mode == 2) {
        M = g_cnt[e];
        A = Abase + (size_t)e * T * K;
        B = Bbase + (size_t)e * N * K;
        tok = g_tok + e * T;
        wts = g_wt + e * T;
    }
    int m0 = blockIdx.y * BM;
    int n0 = blockIdx.x * BN;
    if (m0 >= M) return;

    int tid = threadIdx.x;
    if (tid < BM) {
        int m = m0 + tid;
        int r = (m < M) ? m : (M - 1);
        if (mode == 1) r = tok[r];
        rowA[tid] = A + (size_t)r * K;
    }
    __syncthreads();

    int lane = tid & 31, wid = tid >> 5;
    int m0w = (wid >> 1) * 32;
    int n0w = (wid & 1) * 64;
    int lm = lane >> 2, lj = lane & 3;

    float acc[2][8][4];
#pragma unroll
    for (int mf = 0; mf < 2; mf++)
#pragma unroll
        for (int nf = 0; nf < 8; nf++)
#pragma unroll
            for (int r = 0; r < 4; r++) acc[mf][nf][r] = 0.f;

    // loader mapping: row = tid>>1, k-cols (tid&1)*4 + it*8 .. +3
    int lrow = tid >> 1;
    int c0 = (tid & 1) * 4;
    const float* Arow = rowA[lrow];
    const float* Brow = B + (size_t)(n0 + lrow) * K;

    float4 a_st[4], b_st[4];
#define PREFETCH(kb) do { \
    _Pragma("unroll") \
    for (int it = 0; it < 4; it++) { \
        a_st[it] = *(const float4*)(Arow + (kb) + c0 + it * 8); \
        b_st[it] = *(const float4*)(Brow + (kb) + c0 + it * 8); \
    } } while (0)

#define STORE_SM() do { \
    _Pragma("unroll") \
    for (int it = 0; it < 4; it++) { \
        int cb = c0 + it * 8; \
        int col = (cb & ~7) + ((cb & 4) ? 1 : 0); \
        uint32_t* pa = &As[lrow * KPAD + col]; \
        pa[0] = f2tf(a_st[it].x); pa[2] = f2tf(a_st[it].y); \
        pa[4] = f2tf(a_st[it].z); pa[6] = f2tf(a_st[it].w); \
        uint32_t* pb = &Bs[lrow * KPAD + col]; \
        pb[0] = f2tf(b_st[it].x); pb[2] = f2tf(b_st[it].y); \
        pb[4] = f2tf(b_st[it].z); pb[6] = f2tf(b_st[it].w); \
    } } while (0)

    int ktiles = K / BK;
    PREFETCH(0);
    STORE_SM();
    __syncthreads();

    for (int kt = 0; kt < ktiles; kt++) {
        bool has = (kt + 1 < ktiles);
        if (has) PREFETCH((kt + 1) * BK);

#pragma unroll
        for (int ks = 0; ks < 4; ks++) {
            int cb = ks * 8 + lj * 2;
            uint32_t a[2][4];
#pragma unroll
            for (int mf = 0; mf < 2; mf++) {
                int base = (m0w + mf * 16 + lm) * KPAD + cb;
                uint2 p0 = *(const uint2*)&As[base];
                uint2 p1 = *(const uint2*)&As[base + 8 * KPAD];
                a[mf][0] = p0.x; a[mf][1] = p1.x; a[mf][2] = p0.y; a[mf][3] = p1.y;
            }
            uint32_t b[8][2];
#pragma unroll
            for (int nf = 0; nf < 8; nf++) {
                uint2 q = *(const uint2*)&Bs[(n0w + nf * 8 + lm) * KPAD + cb];
                b[nf][0] = q.x; b[nf][1] = q.y;
            }
#pragma unroll
            for (int mf = 0; mf < 2; mf++)
#pragma unroll
                for (int nf = 0; nf < 8; nf++)
                    mma_tf32(acc[mf][nf], a[mf], b[nf]);
        }
        if (has) {
            __syncthreads();
            STORE_SM();
            __syncthreads();
        }
    }
#undef PREFETCH
#undef STORE_SM

    // epilogue: c0 (m, n), c1 (m, n+1), c2 (m+8, n), c3 (m+8, n+1)
    if (mode == 2) {
#pragma unroll
        for (int mf = 0; mf < 2; mf++) {
            int ms = m0 + m0w + mf * 16 + lm;
#pragma unroll
            for (int half = 0; half < 2; half++) {
                int m = ms + half * 8;
                if (m < M) {
                    int t2 = tok[m];
                    float wgt = wts[m];
#pragma unroll
                    for (int nf = 0; nf < 8; nf++) {
                        int n = n0 + n0w + nf * 8 + lj * 2;
                        float* orow = Cbase + (size_t)t2 * N + n;
                        atomicAdd(orow,     wgt * acc[mf][nf][half * 2]);
                        atomicAdd(orow + 1, wgt * acc[mf][nf][half * 2 + 1]);
                    }
                }
            }
        }
    } else {
        float* C = (mode == 1) ? (Cbase + (size_t)e * T * N) : Cbase;
#pragma unroll
        for (int mf = 0; mf < 2; mf++) {
            int ms = m0 + m0w + mf * 16 + lm;
#pragma unroll
            for (int half = 0; half < 2; half++) {
                int m = ms + half * 8;
                if (m < M) {
#pragma unroll
                    for (int nf = 0; nf < 8; nf++) {
                        int n = n0 + n0w + nf * 8 + lj * 2;
                        float2 v = make_float2(acc[mf][nf][half * 2],
                                               acc[mf][nf][half * 2 + 1]);
                        if (addsrc) {
                            float2 ad = *(const float2*)(addsrc + (size_t)m * N + n);
                            v.x += ad.x; v.y += ad.y;
                        }
                        *(float2*)(C + (size_t)m * N + n) = v;
                    }
                }
            }
        }
    }
}

// ---------------- flash attention (fp32, causal, GQA) ----------------
constexpr int BQ = 64;
constexpr int ATTN_SMEM_BYTES = (3 * 64 * (BQ + 4) + 64 * BQ) * 4;  // 68608

__global__ __launch_bounds__(256, 2) void attn_kernel()
{
    extern __shared__ float sm[];
    float (*Qt)[BQ + 4] = (float (*)[BQ + 4])sm;
    float (*Kt)[BQ + 4] = (float (*)[BQ + 4])(sm + 64 * (BQ + 4));
    float (*Ps)[BQ + 4] = (float (*)[BQ + 4])(sm + 2 * 64 * (BQ + 4));
    float (*Vs)[BQ]     = (float (*)[BQ])(sm + 3 * 64 * (BQ + 4));

    int qb = blockIdx.x;
    int h  = blockIdx.y;
    int kh = h >> 2;  // NH/NKV = 4
    int tid = threadIdx.x, tx = tid & 15, ty = tid >> 4;

    const float* Qg = g_q + ((size_t)h * T + qb * BQ) * HD;
    {
        int i = tid >> 2;
#pragma unroll
        for (int it = 0; it < 4; it++) {
            int d0 = ((tid & 3) + it * 4) * 4;
            float4 v = *(const float4*)(Qg + (size_t)i * HD + d0);
            Qt[d0 + 0][i] = v.x * SM_SCALE;
            Qt[d0 + 1][i] = v.y * SM_SCALE;
            Qt[d0 + 2][i] = v.z * SM_SCALE;
            Qt[d0 + 3][i] = v.w * SM_SCALE;
        }
    }

    float m_i[4], l_i[4], o[4][4];
#pragma unroll
    for (int a = 0; a < 4; a++) {
        m_i[a] = -1e30f;
        l_i[a] = 0.f;
#pragma unroll
        for (int b = 0; b < 4; b++) o[a][b] = 0.f;
    }

    for (int kb = 0; kb <= qb; kb++) {
        __syncthreads();
        const float* Kg = g_k + ((size_t)kh * T + kb * BQ) * HD;
        const float* Vg = g_v + ((size_t)kh * T + kb * BQ) * HD;
        {
            int i = tid >> 2;
#pragma unroll
            for (int it = 0; it < 4; it++) {
                int d0 = ((tid & 3) + it * 4) * 4;
                float4 v = *(const float4*)(Kg + (size_t)i * HD + d0);
                Kt[d0 + 0][i] = v.x;
                Kt[d0 + 1][i] = v.y;
                Kt[d0 + 2][i] = v.z;
                Kt[d0 + 3][i] = v.w;
            }
#pragma unroll
            for (int it = 0; it < 4; it++) {
                int f = tid + it * 256;
                int r = f >> 4, c0 = (f & 15) * 4;
                *(float4*)&Vs[r][c0] = *(const float4*)(Vg + (size_t)r * HD + c0);
            }
        }
        __syncthreads();

        float s[4][4];
#pragma unroll
        for (int a = 0; a < 4; a++)
#pragma unroll
            for (int b = 0; b < 4; b++) s[a][b] = 0.f;
#pragma unroll
        for (int d = 0; d < HD; d++) {
            float4 av = *(const float4*)&Qt[d][ty * 4];
            float4 bv = *(const float4*)&Kt[d][tx * 4];
            float aa[4] = {av.x, av.y, av.z, av.w};
            float bb[4] = {bv.x, bv.y, bv.z, bv.w};
#pragma unroll
            for (int a = 0; a < 4; a++)
#pragma unroll
                for (int b = 0; b < 4; b++)
                    s[a][b] = fmaf(aa[a], bb[b], s[a][b]);
        }
        if (kb == qb) {
#pragma unroll
            for (int a = 0; a < 4; a++)
#pragma unroll
                for (int b = 0; b < 4; b++)
                    if (tx * 4 + b > ty * 4 + a) s[a][b] = -1e30f;
        }

#pragma unroll
        for (int a = 0; a < 4; a++) {
            float rm = fmaxf(fmaxf(s[a][0], s[a][1]), fmaxf(s[a][2], s[a][3]));
#pragma unroll
            for (int off = 1; off < 16; off <<= 1)
                rm = fmaxf(rm, __shfl_xor_sync(0xffffffffu, rm, off, 16));
            float mn = fmaxf(m_i[a], rm);
            float sc = __expf(m_i[a] - mn);
            m_i[a] = mn;
            float rs = 0.f;
#pragma unroll
            for (int b = 0; b < 4; b++) {
                float p = __expf(s[a][b] - mn);
                s[a][b] = p;
                rs += p;
            }
#pragma unroll
            for (int off = 1; off < 16; off <<= 1)
                rs += __shfl_xor_sync(0xffffffffu, rs, off, 16);
            l_i[a] = l_i[a] * sc + rs;
#pragma unroll
            for (int b = 0; b < 4; b++) o[a][b] *= sc;
        }

#pragma unroll
        for (int b = 0; b < 4; b++) {
            float4 pv = make_float4(s[0][b], s[1][b], s[2][b], s[3][b]);
            *(float4*)&Ps[tx * 4 + b][ty * 4] = pv;
        }
        __syncthreads();

#pragma unroll
        for (int kk = 0; kk < BQ; kk++) {
            float4 av = *(const float4*)&Ps[kk][ty * 4];
            float4 bv = *(const float4*)&Vs[kk][tx * 4];
            float aa[4] = {av.x, av.y, av.z, av.w};
            float bb[4] = {bv.x, bv.y, bv.z, bv.w};
#pragma unroll
            for (int a = 0; a < 4; a++)
#pragma unroll
                for (int b = 0; b < 4; b++)
                    o[a][b] = fmaf(aa[a], bb[b], o[a][b]);
        }
    }

#pragma unroll
    for (int a = 0; a < 4; a++) {
        float inv = 1.0f / l_i[a];
        int trow = qb * BQ + ty * 4 + a;
        float* dst = g_attno + (size_t)trow * H + h * HD + tx * 4;
        float4 r = make_float4(o[a][0] * inv, o[a][1] * inv, o[a][2] * inv, o[a][3] * inv);
        *(float4*)dst = r;
    }
}

// ---------------- MoE routing ----------------
__global__ __launch_bounds__(256) void route_kernel(const float* __restrict__ gate_w)
{
    int t = blockIdx.x;
    int wid = threadIdx.x >> 5, lane = threadIdx.x & 31;
    const float* x = g_xn2 + (size_t)t * H;
    const float* g = gate_w + (size_t)wid * H;
    float s = 0.f;
    for (int i = lane; i < H; i += 32) s += x[i] * g[i];
#pragma unroll
    for (int off = 16; off > 0; off >>= 1) s += __shfl_xor_sync(0xffffffffu, s, off);
    __shared__ float logits[NE];
    if (lane == 0) logits[wid] = s;
    __syncthreads();
    if (threadIdx.x == 0) {
        int i1 = 0;
        for (int i = 1; i < NE; i++)
            if (logits[i] > logits[i1]) i1 = i;
        int i2 = (i1 == 0) ? 1 : 0;
        for (int i = 0; i < NE; i++)
            if (i != i1 && logits[i] > logits[i2]) i2 = i;
        float e1 = 1.0f;
        float e2 = expf(logits[i2] - logits[i1]);
        float inv = 1.0f / (e1 + e2);
        float w1v = e1 * inv, w2v = e2 * inv;
        int p1 = atomicAdd(&g_cnt[i1], 1);
        g_tok[i1 * T + p1] = t;
        g_wt [i1 * T + p1] = w1v;
        int p2 = atomicAdd(&g_cnt[i2], 1);
        g_tok[i2 * T + p2] = t;
        g_wt [i2 * T + p2] = w2v;
    }
}

// silu(h1) * h3 in place into g_h1. grid (T, NE), early exit by count.
__global__ __launch_bounds__(256) void silu_kernel()
{
    int e = blockIdx.y, m = blockIdx.x;
    if (m >= g_cnt[e]) return;
    float4* h1 = (float4*)(g_h1 + ((size_t)e * T + m) * F);
    const float4* h3 = (const float4*)(g_h3 + ((size_t)e * T + m) * F);
#pragma unroll
    for (int it = 0; it < 2; it++) {
        int i = threadIdx.x + it * 256;
        float4 a = h1[i], c = h3[i];
        a.x = a.x / (1.f + __expf(-a.x)) * c.x;
        a.y = a.y / (1.f + __expf(-a.y)) * c.y;
        a.z = a.z / (1.f + __expf(-a.z)) * c.z;
        a.w = a.w / (1.f + __expf(-a.w)) * c.w;
        h1[i] = a;
    }
}

// ---------------- launcher ----------------
extern "C" void kernel_launch(void* const* d_in, const int* in_sizes, int n_in,
                              void* d_out, int out_size)
{
    const int*   positions = (const int*)  d_in[0];
    const float* hidden    = (const float*)d_in[1];
    const float* w_qkv     = (const float*)d_in[2];
    const float* w_o       = (const float*)d_in[3];
    const float* norm_in   = (const float*)d_in[4];
    const float* norm_post = (const float*)d_in[5];
    const float* norm_next = (const float*)d_in[6];
    const float* gate_w    = (const float*)d_in[7];
    const float* w1        = (const float*)d_in[8];
    const float* w2        = (const float*)d_in[9];
    const float* w3        = (const float*)d_in[10];
    float* out = (float*)d_out;

    float *p_xn, *p_qkv, *p_attno, *p_x1, *p_xn2, *p_h1, *p_h3, *p_xout;
    cudaGetSymbolAddress((void**)&p_xn,    g_xn);
    cudaGetSymbolAddress((void**)&p_qkv,   g_qkv);
    cudaGetSymbolAddress((void**)&p_attno, g_attno);
    cudaGetSymbolAddress((void**)&p_x1,    g_x1);
    cudaGetSymbolAddress((void**)&p_xn2,   g_xn2);
    cudaGetSymbolAddress((void**)&p_h1,    g_h1);
    cudaGetSymbolAddress((void**)&p_h3,    g_h3);
    cudaGetSymbolAddress((void**)&p_xout,  g_xout);

    cudaFuncSetAttribute(attn_kernel, cudaFuncAttributeMaxDynamicSharedMemorySize,
                         ATTN_SMEM_BYTES);

    // 1) reset routing counts (per replay)
    zero_cnt_kernel<<<1, 32>>>();
    // 2) xn = rmsnorm(hidden, norm_in)
    rmsnorm_kernel<<<T, 256>>>(hidden, norm_in, p_xn, nullptr);
    // 3) qkv = xn @ w_qkv^T
    gemm_tf32_kernel<<<dim3(QKVD / BN, T / BM, 1), 256>>>(0, T, QKVD, H, p_xn, w_qkv, p_qkv, nullptr);
    // 4) rope + split
    rope_kernel<<<T * (NH + 2 * NKV) / 8, 256>>>(p_qkv, positions);
    // 5) attention
    attn_kernel<<<dim3(T / BQ, NH), 256, ATTN_SMEM_BYTES>>>();
    // 6) x1 = hidden + attno @ w_o^T
    gemm_tf32_kernel<<<dim3(H / BN, T / BM, 1), 256>>>(0, T, H, H, p_attno, w_o, p_x1, hidden);
    // 7) xn2 = rmsnorm(x1, norm_post); xout = x1 (residual accumulator init)
    rmsnorm_kernel<<<T, 256>>>(p_x1, norm_post, p_xn2, p_xout);
    // 8) routing (top-2)
    route_kernel<<<T, 256>>>(gate_w);
    // 9/10) h1 = gathered xn2 @ w1^T ; h3 = gathered xn2 @ w3^T
    gemm_tf32_kernel<<<dim3(F / BN, T / BM, NE), 256>>>(1, 0, F, H, p_xn2, w1, p_h1, nullptr);
    gemm_tf32_kernel<<<dim3(F / BN, T / BM, NE), 256>>>(1, 0, F, H, p_xn2, w3, p_h3, nullptr);
    // 11) act = silu(h1) * h3
    silu_kernel<<<dim3(T, NE), 256>>>();
    // 12) xout += wt * (act @ w2^T)  (atomic scatter)
    gemm_tf32_kernel<<<dim3(H / BN, T / BM, NE), 256>>>(2, 0, H, F, p_h1, w2, p_xout, nullptr);
    // 13) out = rmsnorm(xout, norm_next); out[T*H:] = xout
    float* xcopy = (out_size >= 2 * T * H) ? (out + (size_t)T * H) : nullptr;
    rmsnorm_kernel<<<T, 256>>>(p_xout, norm_next, out, xcopy);
}

// round 7
// speedup vs baseline: 1.7515x; 1.1000x over previous
#include <cuda_runtime.h>
#include <math.h>
#include <stdint.h>

// ---------------- problem constants ----------------
constexpr int T    = 2048;
constexpr int H    = 1024;
constexpr int NH   = 16;
constexpr int NKV  = 4;
constexpr int HD   = 64;
constexpr int NE   = 8;
constexpr int F    = 2048;
constexpr int QKVD = (NH + 2 * NKV) * HD;   // 1536
constexpr float EPS = 1e-5f;
constexpr float SM_SCALE = 0.125f;          // HD^-0.5

// ---------------- scratch (device globals; no runtime alloc) ----------------
__device__ float g_xn   [T * H];
__device__ float g_qkv  [T * QKVD];
__device__ float g_q    [NH  * T * HD];
__device__ float g_k    [NKV * T * HD];
__device__ float g_v    [NKV * T * HD];
__device__ float g_attno[T * H];
__device__ float g_x1   [T * H];
__device__ float g_xn2  [T * H];
__device__ float g_h1   [(size_t)NE * T * F];
__device__ float g_h3   [(size_t)NE * T * F];
__device__ float g_xout [T * H];
__device__ int   g_cnt  [NE];
__device__ int   g_tok  [NE * T];
__device__ float g_wt   [NE * T];

// interleave map: (k, k+4) pairs adjacent -> LDS.64 fragment loads
__device__ __forceinline__ int kmap(int k) {
    return (k & ~7) + ((k & 4) ? 1 : 0) + (k & 3) * 2;
}

__device__ __forceinline__ void mma_tf32(float* c, const uint32_t* a, const uint32_t* b) {
    asm volatile(
        "mma.sync.aligned.m16n8k8.row.col.f32.tf32.tf32.f32 "
        "{%0,%1,%2,%3}, {%4,%5,%6,%7}, {%8,%9}, {%0,%1,%2,%3};"
        : "+f"(c[0]), "+f"(c[1]), "+f"(c[2]), "+f"(c[3])
        : "r"(a[0]), "r"(a[1]), "r"(a[2]), "r"(a[3]), "r"(b[0]), "r"(b[1]));
}

// ---------------- misc kernels ----------------
__global__ void zero_cnt_kernel() {
    if (threadIdx.x < NE) g_cnt[threadIdx.x] = 0;
}

__global__ __launch_bounds__(256) void rmsnorm_kernel(
    const float* __restrict__ x, const float* __restrict__ w,
    float* __restrict__ out, float* __restrict__ copy_out)
{
    int row = blockIdx.x;
    int tid = threadIdx.x;
    const float4* xr = (const float4*)(x + (size_t)row * H);
    float4 v = xr[tid];
    float ss = v.x * v.x + v.y * v.y + v.z * v.z + v.w * v.w;
#pragma unroll
    for (int o = 16; o > 0; o >>= 1) ss += __shfl_xor_sync(0xffffffffu, ss, o);
    __shared__ float warpsum[8];
    if ((tid & 31) == 0) warpsum[tid >> 5] = ss;
    __syncthreads();
    if (tid == 0) {
        float s = 0.f;
#pragma unroll
        for (int i = 0; i < 8; i++) s += warpsum[i];
        warpsum[0] = rsqrtf(s / (float)H + EPS);
    }
    __syncthreads();
    float rstd = warpsum[0];
    float4 wv = ((const float4*)w)[tid];
    float4 r;
    r.x = v.x * rstd * wv.x;
    r.y = v.y * rstd * wv.y;
    r.z = v.z * rstd * wv.z;
    r.w = v.w * rstd * wv.w;
    ((float4*)(out + (size_t)row * H))[tid] = r;
    if (copy_out) ((float4*)(copy_out + (size_t)row * H))[tid] = v;
}

__global__ __launch_bounds__(256) void rope_kernel(const float* __restrict__ qkv,
                                                   const int* __restrict__ pos)
{
    int idx = blockIdx.x * 8 + (threadIdx.x >> 5);
    int t = idx / (NH + 2 * NKV);
    int h = idx % (NH + 2 * NKV);
    int lane = threadIdx.x & 31;
    if (h < NH + NKV) {
        float p = (float)pos[t];
        float inv = exp2f(-(float)lane * (13.287712379549449f / 32.0f));
        float ang = p * inv;
        float s, c;
        sincosf(ang, &s, &c);
        const float* src;
        float* dst;
        if (h < NH) {
            src = qkv + (size_t)t * QKVD + h * HD;
            dst = g_q + ((size_t)h * T + t) * HD;
        } else {
            int kh = h - NH;
            src = qkv + (size_t)t * QKVD + NH * HD + kh * HD;
            dst = g_k + ((size_t)kh * T + t) * HD;
        }
        float x1 = src[lane], x2 = src[lane + 32];
        dst[lane]      = x1 * c - x2 * s;
        dst[lane + 32] = x2 * c + x1 * s;
    } else {
        int kh = h - NH - NKV;
        const float* src = qkv + (size_t)t * QKVD + (NH + NKV) * HD + kh * HD;
        float* dst = g_v + ((size_t)kh * T + t) * HD;
        dst[lane]      = src[lane];
        dst[lane + 32] = src[lane + 32];
    }
}

// ---------------- tf32 tensor-core NT GEMM (double-buffered) ----------------
constexpr int BM = 128, BN = 128, BK = 32;
constexpr int KPAD = BK + 8;   // 40
constexpr int GEMM_SMEM = 2 * 2 * BM * KPAD * 4;  // 81920 bytes

__global__ __launch_bounds__(256, 2) void gemm_tf32_kernel(
    int mode, int Mfull, int N, int K,
    const float* __restrict__ Abase, const float* __restrict__ Bbase,
    float* __restrict__ Cbase, const float* __restrict__ addsrc)
{
    extern __shared__ uint32_t dynsm[];
    uint32_t* As = dynsm;                    // [2][BM*KPAD]
    uint32_t* Bs = dynsm + 2 * BM * KPAD;    // [2][BN*KPAD]
    __shared__ const float* rowA[BM];

    int e = blockIdx.z;
    int M = Mfull;
    const float* A = Abase;
    const float* B = Bbase;
    const int* tok = nullptr;
    const float* wts = nullptr;
    if (mode == 1) {
        M = g_cnt[e];
        B = Bbase + (size_t)e * N * K;
        tok = g_tok + e * T;
    } else if (mode == 2) {
        M = g_cnt[e];
        A = Abase + (size_t)e * T * K;
        B = Bbase + (size_t)e * N * K;
        tok = g_tok + e * T;
        wts = g_wt + e * T;
    }
    int m0 = blockIdx.y * BM;
    int n0 = blockIdx.x * BN;
    if (m0 >= M) return;

    int tid = threadIdx.x;
    if (tid < BM) {
        int m = m0 + tid;
        int r = (m < M) ? m : (M - 1);
        if (mode == 1) r = tok[r];
        rowA[tid] = A + (size_t)r * K;
    }
    __syncthreads();

    int lane = tid & 31, wid = tid >> 5;
    int m0w = (wid >> 1) * 32;
    int n0w = (wid & 1) * 64;
    int lm = lane >> 2, lj = lane & 3;

    float acc[2][8][4];
#pragma unroll
    for (int mf = 0; mf < 2; mf++)
#pragma unroll
        for (int nf = 0; nf < 8; nf++)
#pragma unroll
            for (int r = 0; r < 4; r++) acc[mf][nf][r] = 0.f;

    int lrow = tid >> 1;
    int c0 = (tid & 1) * 4;
    const float* Arow = rowA[lrow];
    const float* Brow = B + (size_t)(n0 + lrow) * K;

    float4 a_st[4], b_st[4];
#define PREFETCH(kb) do { \
    _Pragma("unroll") \
    for (int it = 0; it < 4; it++) { \
        a_st[it] = *(const float4*)(Arow + (kb) + c0 + it * 8); \
        b_st[it] = *(const float4*)(Brow + (kb) + c0 + it * 8); \
    } } while (0)

#define STORE_SM(buf) do { \
    uint32_t* Ab = As + (buf) * (BM * KPAD); \
    uint32_t* Bb = Bs + (buf) * (BM * KPAD); \
    _Pragma("unroll") \
    for (int it = 0; it < 4; it++) { \
        int cb = c0 + it * 8; \
        int col = (cb & ~7) + ((cb & 4) ? 1 : 0); \
        uint32_t* pa = &Ab[lrow * KPAD + col]; \
        pa[0] = __float_as_uint(a_st[it].x); pa[2] = __float_as_uint(a_st[it].y); \
        pa[4] = __float_as_uint(a_st[it].z); pa[6] = __float_as_uint(a_st[it].w); \
        uint32_t* pb = &Bb[lrow * KPAD + col]; \
        pb[0] = __float_as_uint(b_st[it].x); pb[2] = __float_as_uint(b_st[it].y); \
        pb[4] = __float_as_uint(b_st[it].z); pb[6] = __float_as_uint(b_st[it].w); \
    } } while (0)

    int ktiles = K / BK;
    PREFETCH(0);
    STORE_SM(0);
    if (ktiles > 1) PREFETCH(BK);
    __syncthreads();

    for (int kt = 0; kt < ktiles; kt++) {
        int buf = kt & 1;
        if (kt + 1 < ktiles) {
            STORE_SM(buf ^ 1);
            if (kt + 2 < ktiles) PREFETCH((kt + 2) * BK);
        }
        const uint32_t* Ab = As + buf * (BM * KPAD);
        const uint32_t* Bb = Bs + buf * (BM * KPAD);
#pragma unroll
        for (int ks = 0; ks < 4; ks++) {
            int cb = ks * 8 + lj * 2;
            uint32_t a[2][4];
#pragma unroll
            for (int mf = 0; mf < 2; mf++) {
                int base = (m0w + mf * 16 + lm) * KPAD + cb;
                uint2 p0 = *(const uint2*)&Ab[base];
                uint2 p1 = *(const uint2*)&Ab[base + 8 * KPAD];
                a[mf][0] = p0.x; a[mf][1] = p1.x; a[mf][2] = p0.y; a[mf][3] = p1.y;
            }
            uint32_t b[8][2];
#pragma unroll
            for (int nf = 0; nf < 8; nf++) {
                uint2 q = *(const uint2*)&Bb[(n0w + nf * 8 + lm) * KPAD + cb];
                b[nf][0] = q.x; b[nf][1] = q.y;
            }
#pragma unroll
            for (int mf = 0; mf < 2; mf++)
#pragma unroll
                for (int nf = 0; nf < 8; nf++)
                    mma_tf32(acc[mf][nf], a[mf], b[nf]);
        }
        __syncthreads();
    }
#undef PREFETCH
#undef STORE_SM

    if (mode == 2) {
#pragma unroll
        for (int mf = 0; mf < 2; mf++) {
            int ms = m0 + m0w + mf * 16 + lm;
#pragma unroll
            for (int half = 0; half < 2; half++) {
                int m = ms + half * 8;
                if (m < M) {
                    int t2 = tok[m];
                    float wgt = wts[m];
#pragma unroll
                    for (int nf = 0; nf < 8; nf++) {
                        int n = n0 + n0w + nf * 8 + lj * 2;
                        float* orow = Cbase + (size_t)t2 * N + n;
                        atomicAdd(orow,     wgt * acc[mf][nf][half * 2]);
                        atomicAdd(orow + 1, wgt * acc[mf][nf][half * 2 + 1]);
                    }
                }
            }
        }
    } else {
        float* C = (mode == 1) ? (Cbase + (size_t)e * T * N) : Cbase;
#pragma unroll
        for (int mf = 0; mf < 2; mf++) {
            int ms = m0 + m0w + mf * 16 + lm;
#pragma unroll
            for (int half = 0; half < 2; half++) {
                int m = ms + half * 8;
                if (m < M) {
#pragma unroll
                    for (int nf = 0; nf < 8; nf++) {
                        int n = n0 + n0w + nf * 8 + lj * 2;
                        float2 v = make_float2(acc[mf][nf][half * 2],
                                               acc[mf][nf][half * 2 + 1]);
                        if (addsrc) {
                            float2 ad = *(const float2*)(addsrc + (size_t)m * N + n);
                            v.x += ad.x; v.y += ad.y;
                        }
                        *(float2*)(C + (size_t)m * N + n) = v;
                    }
                }
            }
        }
    }
}

// ---------------- tf32 tensor-core flash attention ----------------
// CTA: 128 threads (4 warps), Q block 64 rows, K block 64.
// Warp w owns q rows [w*16, w*16+16). S and PV are NT-gemms with the same
// k-pair-interleaved smem fragment layout as gemm_tf32_kernel.
constexpr int AKP = 72;
constexpr int ATTN_SMEM = 4 * 64 * AKP * 4;  // Qs, Ks, Vt, Ps = 73728 bytes

__global__ __launch_bounds__(128) void attn_tc_kernel()
{
    extern __shared__ float smf[];
    float* Qs = smf;                 // [64][AKP] rows=q, cols=hd interleaved
    float* Ks = smf + 64 * AKP;      // [64][AKP] rows=key, cols=hd interleaved
    float* Vt = smf + 2 * 64 * AKP;  // [64][AKP] rows=hd,  cols=key interleaved
    float* Ps = smf + 3 * 64 * AKP;  // [64][AKP] rows=q,   cols=key interleaved

    int qb = blockIdx.x, h = blockIdx.y, kh = h >> 2;
    int tid = threadIdx.x, lane = tid & 31, wid = tid >> 5;
    int lm = lane >> 2, lj = lane & 3;

    // load Q (scaled) into interleaved smem
    {
        const float* Qg = g_q + ((size_t)h * T + qb * 64) * HD;
        int row = tid >> 1;
        int cb0 = (tid & 1) * 4;
#pragma unroll
        for (int it = 0; it < 8; it++) {
            int c = cb0 + it * 8;
            float4 v = *(const float4*)(Qg + (size_t)row * HD + c);
            int base = (c & ~7) + ((c & 4) ? 1 : 0);
            float* pq = &Qs[row * AKP + base];
            pq[0] = v.x * SM_SCALE; pq[2] = v.y * SM_SCALE;
            pq[4] = v.z * SM_SCALE; pq[6] = v.w * SM_SCALE;
        }
    }

    float mi[2] = {-1e30f, -1e30f};
    float li[2] = {0.f, 0.f};
    float o[8][4];
#pragma unroll
    for (int nf = 0; nf < 8; nf++)
#pragma unroll
        for (int r = 0; r < 4; r++) o[nf][r] = 0.f;

    for (int kb = 0; kb <= qb; kb++) {
        __syncthreads();  // previous PV done with Ks/Vt/Ps
        {
            const float* Kg = g_k + ((size_t)kh * T + kb * 64) * HD;
            const float* Vg = g_v + ((size_t)kh * T + kb * 64) * HD;
            int row = tid >> 1;
            int cb0 = (tid & 1) * 4;
            int kmr = kmap(row);
#pragma unroll
            for (int it = 0; it < 8; it++) {
                int c = cb0 + it * 8;
                float4 kv = *(const float4*)(Kg + (size_t)row * HD + c);
                int base = (c & ~7) + ((c & 4) ? 1 : 0);
                float* pk = &Ks[row * AKP + base];
                pk[0] = kv.x; pk[2] = kv.y; pk[4] = kv.z; pk[6] = kv.w;
                float4 vv = *(const float4*)(Vg + (size_t)row * HD + c);
                Vt[(c + 0) * AKP + kmr] = vv.x;
                Vt[(c + 1) * AKP + kmr] = vv.y;
                Vt[(c + 2) * AKP + kmr] = vv.z;
                Vt[(c + 3) * AKP + kmr] = vv.w;
            }
        }
        __syncthreads();

        // S = Q K^T (64x64, this warp: rows wid*16..+15)
        float s[8][4];
#pragma unroll
        for (int nf = 0; nf < 8; nf++)
#pragma unroll
            for (int r = 0; r < 4; r++) s[nf][r] = 0.f;
#pragma unroll
        for (int ks = 0; ks < 8; ks++) {
            int cb = ks * 8 + lj * 2;
            uint32_t a[4];
            {
                const uint32_t* Qu = (const uint32_t*)Qs;
                uint2 p0 = *(const uint2*)&Qu[(wid * 16 + lm) * AKP + cb];
                uint2 p1 = *(const uint2*)&Qu[(wid * 16 + lm + 8) * AKP + cb];
                a[0] = p0.x; a[1] = p1.x; a[2] = p0.y; a[3] = p1.y;
            }
#pragma unroll
            for (int nf = 0; nf < 8; nf++) {
                const uint32_t* Ku = (const uint32_t*)Ks;
                uint2 q = *(const uint2*)&Ku[(nf * 8 + lm) * AKP + cb];
                uint32_t b[2] = {q.x, q.y};
                mma_tf32(s[nf], a, b);
            }
        }

        if (kb == qb) {
            int r0 = wid * 16 + lm;
#pragma unroll
            for (int nf = 0; nf < 8; nf++) {
                int c = nf * 8 + lj * 2;
                if (c     > r0)     s[nf][0] = -1e30f;
                if (c + 1 > r0)     s[nf][1] = -1e30f;
                if (c     > r0 + 8) s[nf][2] = -1e30f;
                if (c + 1 > r0 + 8) s[nf][3] = -1e30f;
            }
        }

        // online softmax (rows r0 = lm and r0+8 per thread; quad = same rows)
        float rm0 = -1e30f, rm1 = -1e30f;
#pragma unroll
        for (int nf = 0; nf < 8; nf++) {
            rm0 = fmaxf(rm0, fmaxf(s[nf][0], s[nf][1]));
            rm1 = fmaxf(rm1, fmaxf(s[nf][2], s[nf][3]));
        }
        rm0 = fmaxf(rm0, __shfl_xor_sync(0xffffffffu, rm0, 1));
        rm0 = fmaxf(rm0, __shfl_xor_sync(0xffffffffu, rm0, 2));
        rm1 = fmaxf(rm1, __shfl_xor_sync(0xffffffffu, rm1, 1));
        rm1 = fmaxf(rm1, __shfl_xor_sync(0xffffffffu, rm1, 2));
        float mn0 = fmaxf(mi[0], rm0), mn1 = fmaxf(mi[1], rm1);
        float sc0 = __expf(mi[0] - mn0), sc1 = __expf(mi[1] - mn1);
        mi[0] = mn0; mi[1] = mn1;
        float rs0 = 0.f, rs1 = 0.f;
#pragma unroll
        for (int nf = 0; nf < 8; nf++) {
            s[nf][0] = __expf(s[nf][0] - mn0); rs0 += s[nf][0];
            s[nf][1] = __expf(s[nf][1] - mn0); rs0 += s[nf][1];
            s[nf][2] = __expf(s[nf][2] - mn1); rs1 += s[nf][2];
            s[nf][3] = __expf(s[nf][3] - mn1); rs1 += s[nf][3];
        }
        rs0 += __shfl_xor_sync(0xffffffffu, rs0, 1);
        rs0 += __shfl_xor_sync(0xffffffffu, rs0, 2);
        rs1 += __shfl_xor_sync(0xffffffffu, rs1, 1);
        rs1 += __shfl_xor_sync(0xffffffffu, rs1, 2);
        li[0] = li[0] * sc0 + rs0;
        li[1] = li[1] * sc1 + rs1;
#pragma unroll
        for (int nf = 0; nf < 8; nf++) {
            o[nf][0] *= sc0; o[nf][1] *= sc0;
            o[nf][2] *= sc1; o[nf][3] *= sc1;
        }

        // write P to interleaved smem (rows=q local, cols=key local)
#pragma unroll
        for (int nf = 0; nf < 8; nf++) {
            int n = nf * 8 + lj * 2;
            int k0 = kmap(n), k1 = kmap(n + 1);
            int rbase = (wid * 16 + lm) * AKP;
            Ps[rbase + k0]           = s[nf][0];
            Ps[rbase + k1]           = s[nf][1];
            Ps[rbase + 8 * AKP + k0] = s[nf][2];
            Ps[rbase + 8 * AKP + k1] = s[nf][3];
        }
        __syncthreads();

        // O += P V  (A = Ps rows=q cols=key; B = Vt rows=hd cols=key)
#pragma unroll
        for (int ks = 0; ks < 8; ks++) {
            int cb = ks * 8 + lj * 2;
            uint32_t a[4];
            {
                const uint32_t* Pu = (const uint32_t*)Ps;
                uint2 p0 = *(const uint2*)&Pu[(wid * 16 + lm) * AKP + cb];
                uint2 p1 = *(const uint2*)&Pu[(wid * 16 + lm + 8) * AKP + cb];
                a[0] = p0.x; a[1] = p1.x; a[2] = p0.y; a[3] = p1.y;
            }
#pragma unroll
            for (int nf = 0; nf < 8; nf++) {
                const uint32_t* Vu = (const uint32_t*)Vt;
                uint2 q = *(const uint2*)&Vu[(nf * 8 + lm) * AKP + cb];
                uint32_t b[2] = {q.x, q.y};
                mma_tf32(o[nf], a, b);
            }
        }
    }

    // normalize + write out
    float inv0 = 1.0f / li[0], inv1 = 1.0f / li[1];
    int row0 = qb * 64 + wid * 16 + lm;
#pragma unroll
    for (int nf = 0; nf < 8; nf++) {
        int col = h * HD + nf * 8 + lj * 2;
        float2 v0 = make_float2(o[nf][0] * inv0, o[nf][1] * inv0);
        float2 v1 = make_float2(o[nf][2] * inv1, o[nf][3] * inv1);
        *(float2*)&g_attno[(size_t)row0 * H + col] = v0;
        *(float2*)&g_attno[(size_t)(row0 + 8) * H + col] = v1;
    }
}

// ---------------- MoE routing ----------------
__global__ __launch_bounds__(256) void route_kernel(const float* __restrict__ gate_w)
{
    int t = blockIdx.x;
    int wid = threadIdx.x >> 5, lane = threadIdx.x & 31;
    const float* x = g_xn2 + (size_t)t * H;
    const float* g = gate_w + (size_t)wid * H;
    float s = 0.f;
    for (int i = lane; i < H; i += 32) s += x[i] * g[i];
#pragma unroll
    for (int off = 16; off > 0; off >>= 1) s += __shfl_xor_sync(0xffffffffu, s, off);
    __shared__ float logits[NE];
    if (lane == 0) logits[wid] = s;
    __syncthreads();
    if (threadIdx.x == 0) {
        int i1 = 0;
        for (int i = 1; i < NE; i++)
            if (logits[i] > logits[i1]) i1 = i;
        int i2 = (i1 == 0) ? 1 : 0;
        for (int i = 0; i < NE; i++)
            if (i != i1 && logits[i] > logits[i2]) i2 = i;
        float e1 = 1.0f;
        float e2 = expf(logits[i2] - logits[i1]);
        float inv = 1.0f / (e1 + e2);
        float w1v = e1 * inv, w2v = e2 * inv;
        int p1 = atomicAdd(&g_cnt[i1], 1);
        g_tok[i1 * T + p1] = t;
        g_wt [i1 * T + p1] = w1v;
        int p2 = atomicAdd(&g_cnt[i2], 1);
        g_tok[i2 * T + p2] = t;
        g_wt [i2 * T + p2] = w2v;
    }
}

__global__ __launch_bounds__(256) void silu_kernel()
{
    int e = blockIdx.y, m = blockIdx.x;
    if (m >= g_cnt[e]) return;
    float4* h1 = (float4*)(g_h1 + ((size_t)e * T + m) * F);
    const float4* h3 = (const float4*)(g_h3 + ((size_t)e * T + m) * F);
#pragma unroll
    for (int it = 0; it < 2; it++) {
        int i = threadIdx.x + it * 256;
        float4 a = h1[i], c = h3[i];
        a.x = a.x / (1.f + __expf(-a.x)) * c.x;
        a.y = a.y / (1.f + __expf(-a.y)) * c.y;
        a.z = a.z / (1.f + __expf(-a.z)) * c.z;
        a.w = a.w / (1.f + __expf(-a.w)) * c.w;
        h1[i] = a;
    }
}

// ---------------- launcher ----------------
extern "C" void kernel_launch(void* const* d_in, const int* in_sizes, int n_in,
                              void* d_out, int out_size)
{
    const int*   positions = (const int*)  d_in[0];
    const float* hidden    = (const float*)d_in[1];
    const float* w_qkv     = (const float*)d_in[2];
    const float* w_o       = (const float*)d_in[3];
    const float* norm_in   = (const float*)d_in[4];
    const float* norm_post = (const float*)d_in[5];
    const float* norm_next = (const float*)d_in[6];
    const float* gate_w    = (const float*)d_in[7];
    const float* w1        = (const float*)d_in[8];
    const float* w2        = (const float*)d_in[9];
    const float* w3        = (const float*)d_in[10];
    float* out = (float*)d_out;

    float *p_xn, *p_qkv, *p_attno, *p_x1, *p_xn2, *p_h1, *p_h3, *p_xout;
    cudaGetSymbolAddress((void**)&p_xn,    g_xn);
    cudaGetSymbolAddress((void**)&p_qkv,   g_qkv);
    cudaGetSymbolAddress((void**)&p_attno, g_attno);
    cudaGetSymbolAddress((void**)&p_x1,    g_x1);
    cudaGetSymbolAddress((void**)&p_xn2,   g_xn2);
    cudaGetSymbolAddress((void**)&p_h1,    g_h1);
    cudaGetSymbolAddress((void**)&p_h3,    g_h3);
    cudaGetSymbolAddress((void**)&p_xout,  g_xout);

    cudaFuncSetAttribute(gemm_tf32_kernel, cudaFuncAttributeMaxDynamicSharedMemorySize,
                         GEMM_SMEM);
    cudaFuncSetAttribute(attn_tc_kernel, cudaFuncAttributeMaxDynamicSharedMemorySize,
                         ATTN_SMEM);

    zero_cnt_kernel<<<1, 32>>>();
    rmsnorm_kernel<<<T, 256>>>(hidden, norm_in, p_xn, nullptr);
    gemm_tf32_kernel<<<dim3(QKVD / BN, T / BM, 1), 256, GEMM_SMEM>>>(
        0, T, QKVD, H, p_xn, w_qkv, p_qkv, nullptr);
    rope_kernel<<<T * (NH + 2 * NKV) / 8, 256>>>(p_qkv, positions);
    attn_tc_kernel<<<dim3(T / 64, NH), 128, ATTN_SMEM>>>();
    gemm_tf32_kernel<<<dim3(H / BN, T / BM, 1), 256, GEMM_SMEM>>>(
        0, T, H, H, p_attno, w_o, p_x1, hidden);
    rmsnorm_kernel<<<T, 256>>>(p_x1, norm_post, p_xn2, p_xout);
    route_kernel<<<T, 256>>>(gate_w);
    gemm_tf32_kernel<<<dim3(F / BN, T / BM, NE), 256, GEMM_SMEM>>>(
        1, 0, F, H, p_xn2, w1, p_h1, nullptr);
    gemm_tf32_kernel<<<dim3(F / BN, T / BM, NE), 256, GEMM_SMEM>>>(
        1, 0, F, H, p_xn2, w3, p_h3, nullptr);
    silu_kernel<<<dim3(T, NE), 256>>>();
    gemm_tf32_kernel<<<dim3(H / BN, T / BM, NE), 256, GEMM_SMEM>>>(
        2, 0, H, F, p_h1, w2, p_xout, nullptr);
    float* xcopy = (out_size >= 2 * T * H) ? (out + (size_t)T * H) : nullptr;
    rmsnorm_kernel<<<T, 256>>>(p_xout, norm_next, out, xcopy);
}